// round 4
// baseline (speedup 1.0000x reference)
#include <cuda_runtime.h>

// Performer / FAVOR+ attention, fp32, GB300 sm_103a.
// B=2 H=16 N=4096 D=64 F=256. Three launches:
//   1) favor_k_kernel : k' = softmax_kernel(K@P); partial kv = k'^T V, ksum = sum k'
//   2) favor_reduce   : deterministic reduction of per-split partials
//   3) favor_q_kernel : q' = softmax_kernel(Q@P); out = (q'@kv) / (q'.(ksum+1e-6))

#define TBLK   256
#define BHN    32
#define NSEQ   4096
#define DDIM   64
#define FDIM   256
#define NSPLIT 32
#define RPB    (NSEQ / NSPLIT)   // 128 rows per block
#define CHUNK  64
#define NCHUNK (RPB / CHUNK)     // 2
#define XPAD   68                // padded row stride for transposed X tile

// Static device scratch (allocation-free contract).
__device__ float g_part_kv[(size_t)BHN * NSPLIT * FDIM * DDIM]; // 67 MB
__device__ float g_part_ks[(size_t)BHN * NSPLIT * FDIM];
__device__ float g_kv[(size_t)BHN * FDIM * DDIM];
__device__ float g_ks[(size_t)BHN * FDIM];

// ---------------------------------------------------------------------------
// GEMM1: S[64][256] = X[64][64] @ P[64][256], 8x8 register tile per thread.
// Thread (rg = tid>>5 in 0..7, cg = tid&31) owns
//   rows {rg*4+i, 32+rg*4+i}, cols {cg*4+j, 128+cg*4+j}  (i,j in 0..3)
// XsT is X transposed [d][row] with row-stride XPAD (float4-aligned).
// ---------------------------------------------------------------------------
__device__ __forceinline__ void proj_gemm(const float* __restrict__ XsT,
                                          const float* __restrict__ Ps,
                                          int rg, int cg,
                                          float acc[2][2][4][4])
{
#pragma unroll
    for (int hr = 0; hr < 2; hr++)
#pragma unroll
        for (int hc = 0; hc < 2; hc++)
#pragma unroll
            for (int i = 0; i < 4; i++)
#pragma unroll
                for (int j = 0; j < 4; j++) acc[hr][hc][i][j] = 0.f;

#pragma unroll 8
    for (int d = 0; d < DDIM; d++) {
        float4 A0 = *(const float4*)(XsT + d * XPAD + rg * 4);        // broadcast in warp
        float4 A1 = *(const float4*)(XsT + d * XPAD + 32 + rg * 4);
        float4 B0 = *(const float4*)(Ps + d * FDIM + cg * 4);         // conflict-free
        float4 B1 = *(const float4*)(Ps + d * FDIM + 128 + cg * 4);
        float av[2][4] = {{A0.x, A0.y, A0.z, A0.w}, {A1.x, A1.y, A1.z, A1.w}};
        float bv[2][4] = {{B0.x, B0.y, B0.z, B0.w}, {B1.x, B1.y, B1.z, B1.w}};
#pragma unroll
        for (int hr = 0; hr < 2; hr++)
#pragma unroll
            for (int i = 0; i < 4; i++)
#pragma unroll
                for (int hc = 0; hc < 2; hc++)
#pragma unroll
                    for (int j = 0; j < 4; j++)
                        acc[hr][hc][i][j] = fmaf(av[hr][i], bv[hc][j], acc[hr][hc][i][j]);
    }
}

// Row-max across the warp (each row's 256 cols live in one warp), then exp/16.
__device__ __forceinline__ void maxexp_rows(float acc[2][2][4][4])
{
#pragma unroll
    for (int hr = 0; hr < 2; hr++)
#pragma unroll
        for (int i = 0; i < 4; i++) {
            float m = acc[hr][0][i][0];
#pragma unroll
            for (int hc = 0; hc < 2; hc++)
#pragma unroll
                for (int j = 0; j < 4; j++) m = fmaxf(m, acc[hr][hc][i][j]);
#pragma unroll
            for (int off = 16; off > 0; off >>= 1)
                m = fmaxf(m, __shfl_xor_sync(0xffffffffu, m, off));
#pragma unroll
            for (int hc = 0; hc < 2; hc++)
#pragma unroll
                for (int j = 0; j < 4; j++)
                    acc[hr][hc][i][j] = __expf(acc[hr][hc][i][j] - m) * 0.0625f; // 1/sqrt(256)
        }
}

// Store the 8x8 register tile into E[64][256] row-major (conflict-free float4).
__device__ __forceinline__ void store_E(float* __restrict__ Es, int rg, int cg,
                                        const float acc[2][2][4][4])
{
#pragma unroll
    for (int hr = 0; hr < 2; hr++)
#pragma unroll
        for (int i = 0; i < 4; i++) {
            int r = hr * 32 + rg * 4 + i;
#pragma unroll
            for (int hc = 0; hc < 2; hc++) {
                *(float4*)(Es + r * FDIM + hc * 128 + cg * 4) =
                    make_float4(acc[hr][hc][i][0], acc[hr][hc][i][1],
                                acc[hr][hc][i][2], acc[hr][hc][i][3]);
            }
        }
}

// Load a 64x64 chunk transposed into XsT[d][r] (stride XPAD).
__device__ __forceinline__ void load_chunk_T(const float* __restrict__ src,
                                             float* __restrict__ XsT, int tid)
{
#pragma unroll
    for (int it = 0; it < (CHUNK * DDIM) / TBLK; it++) {
        int idx = tid + it * TBLK;
        int r = idx >> 6, d = idx & 63;
        XsT[d * XPAD + r] = src[r * DDIM + d];
    }
}

// ---------------------------------------------------------------------------
// Kernel A: k-side. smem = P(64K) + XsT(17K) + E(64K) + V(16K) = 164864 B
// ---------------------------------------------------------------------------
__global__ __launch_bounds__(TBLK, 1)
void favor_k_kernel(const float* __restrict__ K, const float* __restrict__ V,
                    const float* __restrict__ P)
{
    extern __shared__ float sm[];
    float* Ps  = sm;                    // [64][256]
    float* XsT = Ps + DDIM * FDIM;      // [64][XPAD]
    float* Es  = XsT + DDIM * XPAD;     // [64][256]
    float* Vs  = Es + CHUNK * FDIM;     // [64][64]

    const int tid = threadIdx.x;
    const int split = blockIdx.x, bh = blockIdx.y;
    const float* kb = K + (size_t)bh * NSEQ * DDIM;
    const float* vb = V + (size_t)bh * NSEQ * DDIM;

    {
        const float4* src = (const float4*)P;
        float4* dst = (float4*)Ps;
#pragma unroll
        for (int it = 0; it < (DDIM * FDIM / 4) / TBLK; it++)
            dst[tid + it * TBLK] = src[tid + it * TBLK];
    }

    const int rg = tid >> 5, cg = tid & 31;   // GEMM1 mapping
    const int fg = tid >> 3, dg = tid & 7;    // GEMM2 mapping

    float kvacc[2][2][4][4];
    float ksacc[2][4];
#pragma unroll
    for (int hf = 0; hf < 2; hf++)
#pragma unroll
        for (int i = 0; i < 4; i++) {
            ksacc[hf][i] = 0.f;
#pragma unroll
            for (int hd = 0; hd < 2; hd++)
#pragma unroll
                for (int j = 0; j < 4; j++) kvacc[hf][hd][i][j] = 0.f;
        }

    for (int c = 0; c < NCHUNK; c++) {
        const int n0 = split * RPB + c * CHUNK;
        __syncthreads();
        load_chunk_T(kb + (size_t)n0 * DDIM, XsT, tid);
        {   // V chunk: contiguous copy
            const float4* src = (const float4*)(vb + (size_t)n0 * DDIM);
            float4* dst = (float4*)Vs;
#pragma unroll
            for (int it = 0; it < (CHUNK * DDIM / 4) / TBLK; it++)
                dst[tid + it * TBLK] = src[tid + it * TBLK];
        }
        __syncthreads();

        float acc[2][2][4][4];
        proj_gemm(XsT, Ps, rg, cg, acc);
        maxexp_rows(acc);
        store_E(Es, rg, cg, acc);
        __syncthreads();

        // GEMM2: kv[f][d] += sum_r E[r][f] * V[r][d]; ksum[f] += sum_r E[r][f]
#pragma unroll 4
        for (int r = 0; r < CHUNK; r++) {
            float4 A0 = *(const float4*)(Es + r * FDIM + fg * 4);
            float4 A1 = *(const float4*)(Es + r * FDIM + 128 + fg * 4);
            float4 B0 = *(const float4*)(Vs + r * DDIM + dg * 4);
            float4 B1 = *(const float4*)(Vs + r * DDIM + 32 + dg * 4);
            float av[2][4] = {{A0.x, A0.y, A0.z, A0.w}, {A1.x, A1.y, A1.z, A1.w}};
            float bv[2][4] = {{B0.x, B0.y, B0.z, B0.w}, {B1.x, B1.y, B1.z, B1.w}};
#pragma unroll
            for (int hf = 0; hf < 2; hf++)
#pragma unroll
                for (int i = 0; i < 4; i++) {
                    ksacc[hf][i] += av[hf][i];
#pragma unroll
                    for (int hd = 0; hd < 2; hd++)
#pragma unroll
                        for (int j = 0; j < 4; j++)
                            kvacc[hf][hd][i][j] = fmaf(av[hf][i], bv[hd][j], kvacc[hf][hd][i][j]);
                }
        }
    }

    // Write per-split partials (no atomics -> deterministic)
    float* pkv = g_part_kv + ((size_t)(bh * NSPLIT + split)) * FDIM * DDIM;
    float* pks = g_part_ks + (size_t)(bh * NSPLIT + split) * FDIM;
#pragma unroll
    for (int hf = 0; hf < 2; hf++)
#pragma unroll
        for (int i = 0; i < 4; i++) {
            int f = hf * 128 + fg * 4 + i;
#pragma unroll
            for (int hd = 0; hd < 2; hd++) {
                int d = hd * 32 + dg * 4;
                *(float4*)(pkv + f * DDIM + d) =
                    make_float4(kvacc[hf][hd][i][0], kvacc[hf][hd][i][1],
                                kvacc[hf][hd][i][2], kvacc[hf][hd][i][3]);
            }
            if (dg == 0) pks[f] = ksacc[hf][i];
        }
}

// ---------------------------------------------------------------------------
// Reduce: sum NSPLIT partials deterministically; add 1e-6 to ksum here.
// ---------------------------------------------------------------------------
__global__ void favor_reduce_kernel()
{
    int idx = blockIdx.x * blockDim.x + threadIdx.x;
    if (idx < BHN * FDIM * DDIM) {
        int bh = idx / (FDIM * DDIM), r = idx % (FDIM * DDIM);
        float s = 0.f;
#pragma unroll 8
        for (int sp = 0; sp < NSPLIT; sp++)
            s += g_part_kv[((size_t)bh * NSPLIT + sp) * FDIM * DDIM + r];
        g_kv[idx] = s;
    }
    if (idx < BHN * FDIM) {
        int bh = idx / FDIM, f = idx % FDIM;
        float s = 0.f;
#pragma unroll 8
        for (int sp = 0; sp < NSPLIT; sp++)
            s += g_part_ks[(bh * NSPLIT + sp) * FDIM + f];
        g_ks[idx] = s + 1e-6f;
    }
}

// ---------------------------------------------------------------------------
// Kernel B: q-side + output.
// smem = P(64K) + kv(64K) + XsT(17K) + E(64K) + kse(1K) + dnm = 215296 B
// ---------------------------------------------------------------------------
__global__ __launch_bounds__(TBLK, 1)
void favor_q_kernel(const float* __restrict__ Q, const float* __restrict__ P,
                    float* __restrict__ Out)
{
    extern __shared__ float sm[];
    float* Ps  = sm;                    // [64][256]
    float* KVs = Ps + DDIM * FDIM;      // [256][64]
    float* XsT = KVs + FDIM * DDIM;     // [64][XPAD]
    float* Es  = XsT + DDIM * XPAD;     // [64][256]
    float* KSe = Es + CHUNK * FDIM;     // [256]
    float* Dnm = KSe + FDIM;            // [64]

    const int tid = threadIdx.x;
    const int split = blockIdx.x, bh = blockIdx.y;
    const float* qb = Q + (size_t)bh * NSEQ * DDIM;
    float* ob = Out + (size_t)bh * NSEQ * DDIM;

    {
        const float4* src = (const float4*)P;
        float4* dst = (float4*)Ps;
#pragma unroll
        for (int it = 0; it < (DDIM * FDIM / 4) / TBLK; it++)
            dst[tid + it * TBLK] = src[tid + it * TBLK];
        const float4* ksrc = (const float4*)(g_kv + (size_t)bh * FDIM * DDIM);
        float4* kdst = (float4*)KVs;
#pragma unroll
        for (int it = 0; it < (FDIM * DDIM / 4) / TBLK; it++)
            kdst[tid + it * TBLK] = ksrc[tid + it * TBLK];
        KSe[tid] = g_ks[bh * FDIM + tid];   // includes +1e-6
    }

    const int rg = tid >> 5, cg = tid & 31;
    const int w = tid >> 5, lane = tid & 31;

    for (int c = 0; c < NCHUNK; c++) {
        const int n0 = split * RPB + c * CHUNK;
        __syncthreads();
        load_chunk_T(qb + (size_t)n0 * DDIM, XsT, tid);
        __syncthreads();

        float acc[2][2][4][4];
        proj_gemm(XsT, Ps, rg, cg, acc);
        maxexp_rows(acc);

        // denom[r] = sum_f E[r][f] * kse[f]  (folded into GEMM1 epilogue)
        {
            float4 K0 = *(const float4*)(KSe + cg * 4);
            float4 K1 = *(const float4*)(KSe + 128 + cg * 4);
            float kv0[4] = {K0.x, K0.y, K0.z, K0.w};
            float kv1[4] = {K1.x, K1.y, K1.z, K1.w};
#pragma unroll
            for (int hr = 0; hr < 2; hr++)
#pragma unroll
                for (int i = 0; i < 4; i++) {
                    float dn = 0.f;
#pragma unroll
                    for (int j = 0; j < 4; j++)
                        dn += acc[hr][0][i][j] * kv0[j] + acc[hr][1][i][j] * kv1[j];
#pragma unroll
                    for (int off = 16; off > 0; off >>= 1)
                        dn += __shfl_xor_sync(0xffffffffu, dn, off);
                    if (cg == 0) Dnm[hr * 32 + rg * 4 + i] = dn;
                }
        }
        store_E(Es, rg, cg, acc);
        __syncthreads();

        // GEMM3: out[r][d] = sum_f E[r][f] * kv[f][d]; warp w owns rows w*8..w*8+7
        float oa[8][2];
#pragma unroll
        for (int i = 0; i < 8; i++) { oa[i][0] = 0.f; oa[i][1] = 0.f; }
#pragma unroll 2
        for (int f0 = 0; f0 < FDIM; f0 += 4) {
            float4 a[8];
#pragma unroll
            for (int i = 0; i < 8; i++)
                a[i] = *(const float4*)(Es + (w * 8 + i) * FDIM + f0); // warp-broadcast
            float b0[4], b1[4];
#pragma unroll
            for (int u = 0; u < 4; u++) {
                b0[u] = KVs[(f0 + u) * DDIM + lane];          // conflict-free
                b1[u] = KVs[(f0 + u) * DDIM + 32 + lane];
            }
#pragma unroll
            for (int i = 0; i < 8; i++) {
                float av[4] = {a[i].x, a[i].y, a[i].z, a[i].w};
#pragma unroll
                for (int u = 0; u < 4; u++) {
                    oa[i][0] = fmaf(av[u], b0[u], oa[i][0]);
                    oa[i][1] = fmaf(av[u], b1[u], oa[i][1]);
                }
            }
        }
#pragma unroll
        for (int i = 0; i < 8; i++) {
            float rz = 1.0f / Dnm[w * 8 + i];
            size_t r = (size_t)(n0 + w * 8 + i) * DDIM;
            ob[r + lane]      = oa[i][0] * rz;
            ob[r + 32 + lane] = oa[i][1] * rz;
        }
    }
}

// ---------------------------------------------------------------------------
extern "C" void kernel_launch(void* const* d_in, const int* in_sizes, int n_in,
                              void* d_out, int out_size)
{
    const float* q = (const float*)d_in[0];
    const float* k = (const float*)d_in[1];
    const float* v = (const float*)d_in[2];
    const float* P = (const float*)d_in[3];
    float* out = (float*)d_out;

    const int A_SMEM = (DDIM * FDIM + DDIM * XPAD + CHUNK * FDIM + CHUNK * DDIM) * 4;
    const int B_SMEM = (DDIM * FDIM + FDIM * DDIM + DDIM * XPAD + CHUNK * FDIM + FDIM + 64) * 4;

    cudaFuncSetAttribute(favor_k_kernel, cudaFuncAttributeMaxDynamicSharedMemorySize, A_SMEM);
    cudaFuncSetAttribute(favor_q_kernel, cudaFuncAttributeMaxDynamicSharedMemorySize, B_SMEM);

    dim3 grid(NSPLIT, BHN);
    favor_k_kernel<<<grid, TBLK, A_SMEM>>>(k, v, P);
    favor_reduce_kernel<<<(BHN * FDIM * DDIM + 255) / 256, 256>>>();
    favor_q_kernel<<<grid, TBLK, B_SMEM>>>(q, P, out);
}

// round 5
// speedup vs baseline: 1.0680x; 1.0680x over previous
#include <cuda_runtime.h>

// Performer / FAVOR+ attention, fp32, GB300 sm_103a.
// Round 4: packed fma.rn.f32x2 (FFMA2) in all three GEMMs — 2 fp32 FMAs per
// fma-pipe issue slot (ptxas never emits FFMA2 from scalar C++; PTX-only).
//
//   1) favor_k_kernel : k' = softmax_kernel(K@P); partial kv = k'^T V, ksum
//   2) favor_reduce   : deterministic reduction of per-split partials
//   3) favor_q_kernel : q' = softmax_kernel(Q@P); out = (q'@kv)/(q'.(ksum+1e-6))

#define TBLK   256
#define BHN    32
#define NSEQ   4096
#define DDIM   64
#define FDIM   256
#define NSPLIT 32
#define RPB    (NSEQ / NSPLIT)   // 128 rows per block
#define CHUNK  64
#define NCHUNK (RPB / CHUNK)     // 2
#define XPAD   68                // padded row stride for transposed X tile

typedef unsigned long long u64;

// Static device scratch (allocation-free contract).
__device__ float g_part_kv[(size_t)BHN * NSPLIT * FDIM * DDIM]; // 67 MB
__device__ float g_part_ks[(size_t)BHN * NSPLIT * FDIM];
__device__ float g_kv[(size_t)BHN * FDIM * DDIM];
__device__ float g_ks[(size_t)BHN * FDIM];

// ---------------- packed f32x2 helpers ----------------
__device__ __forceinline__ u64 pk2(float lo, float hi) {
    u64 r; asm("mov.b64 %0, {%1,%2};" : "=l"(r) : "f"(lo), "f"(hi)); return r;
}
__device__ __forceinline__ u64 dup2(float x) { return pk2(x, x); }
__device__ __forceinline__ void upk2(float& lo, float& hi, u64 v) {
    asm("mov.b64 {%0,%1}, %2;" : "=f"(lo), "=f"(hi) : "l"(v));
}
__device__ __forceinline__ void ffma2(u64& d, u64 a, u64 b) {
    asm("fma.rn.f32x2 %0, %1, %2, %0;" : "+l"(d) : "l"(a), "l"(b));
}
__device__ __forceinline__ void fadd2(u64& d, u64 a) {
    asm("add.rn.f32x2 %0, %1, %2;" : "=l"(d) : "l"(d), "l"(a));
}

// ---------------------------------------------------------------------------
// GEMM1 (packed): S[64][256] = X[64][64] @ P[64][256].
// Thread (rg = tid>>5, cg = tid&31) owns rows {rg*4+i, 32+rg*4+i},
// cols {cg*4+j, 128+cg*4+j}. Row pairs packed in f32x2 lanes:
// accp[hr][i2][hc][j] lanes = rows (base+2*i2, base+2*i2+1).
// a-pairs come free from contiguous XsT float4 loads (reinterpreted u64x2);
// b scalars are lane-duplicated (1 MOV each, alu pipe).
// ---------------------------------------------------------------------------
__device__ __forceinline__ void proj_gemm_pk(const float* __restrict__ XsT,
                                             const float* __restrict__ Ps,
                                             int rg, int cg,
                                             u64 accp[2][2][2][4])
{
#pragma unroll
    for (int hr = 0; hr < 2; hr++)
#pragma unroll
        for (int i2 = 0; i2 < 2; i2++)
#pragma unroll
            for (int hc = 0; hc < 2; hc++)
#pragma unroll
                for (int j = 0; j < 4; j++) accp[hr][i2][hc][j] = 0ull;

#pragma unroll 8
    for (int d = 0; d < DDIM; d++) {
        ulonglong2 A0 = *(const ulonglong2*)(XsT + d * XPAD + rg * 4);      // rows, bcast
        ulonglong2 A1 = *(const ulonglong2*)(XsT + d * XPAD + 32 + rg * 4);
        u64 ap[2][2] = {{A0.x, A0.y}, {A1.x, A1.y}};
        float4 B0 = *(const float4*)(Ps + d * FDIM + cg * 4);               // conflict-free
        float4 B1 = *(const float4*)(Ps + d * FDIM + 128 + cg * 4);
        u64 bd[2][4] = {{dup2(B0.x), dup2(B0.y), dup2(B0.z), dup2(B0.w)},
                        {dup2(B1.x), dup2(B1.y), dup2(B1.z), dup2(B1.w)}};
#pragma unroll
        for (int hr = 0; hr < 2; hr++)
#pragma unroll
            for (int i2 = 0; i2 < 2; i2++)
#pragma unroll
                for (int hc = 0; hc < 2; hc++)
#pragma unroll
                    for (int j = 0; j < 4; j++)
                        ffma2(accp[hr][i2][hc][j], ap[hr][i2], bd[hc][j]);
    }
}

// Unpack packed GEMM1 accumulators into the scalar [2][2][4][4] layout.
__device__ __forceinline__ void unpack_acc(const u64 accp[2][2][2][4],
                                           float acc[2][2][4][4])
{
#pragma unroll
    for (int hr = 0; hr < 2; hr++)
#pragma unroll
        for (int i2 = 0; i2 < 2; i2++)
#pragma unroll
            for (int hc = 0; hc < 2; hc++)
#pragma unroll
                for (int j = 0; j < 4; j++)
                    upk2(acc[hr][hc][2 * i2][j], acc[hr][hc][2 * i2 + 1][j],
                         accp[hr][i2][hc][j]);
}

// Row-max across the warp (each row's 256 cols live in one warp), then exp/16.
__device__ __forceinline__ void maxexp_rows(float acc[2][2][4][4])
{
#pragma unroll
    for (int hr = 0; hr < 2; hr++)
#pragma unroll
        for (int i = 0; i < 4; i++) {
            float m = acc[hr][0][i][0];
#pragma unroll
            for (int hc = 0; hc < 2; hc++)
#pragma unroll
                for (int j = 0; j < 4; j++) m = fmaxf(m, acc[hr][hc][i][j]);
#pragma unroll
            for (int off = 16; off > 0; off >>= 1)
                m = fmaxf(m, __shfl_xor_sync(0xffffffffu, m, off));
#pragma unroll
            for (int hc = 0; hc < 2; hc++)
#pragma unroll
                for (int j = 0; j < 4; j++)
                    acc[hr][hc][i][j] = __expf(acc[hr][hc][i][j] - m) * 0.0625f; // 1/sqrt(256)
        }
}

// Store the 8x8 register tile into E[64][256] row-major (conflict-free float4).
__device__ __forceinline__ void store_E(float* __restrict__ Es, int rg, int cg,
                                        const float acc[2][2][4][4])
{
#pragma unroll
    for (int hr = 0; hr < 2; hr++)
#pragma unroll
        for (int i = 0; i < 4; i++) {
            int r = hr * 32 + rg * 4 + i;
#pragma unroll
            for (int hc = 0; hc < 2; hc++) {
                *(float4*)(Es + r * FDIM + hc * 128 + cg * 4) =
                    make_float4(acc[hr][hc][i][0], acc[hr][hc][i][1],
                                acc[hr][hc][i][2], acc[hr][hc][i][3]);
            }
        }
}

// Load a 64x64 chunk transposed into XsT[d][r] (stride XPAD).
__device__ __forceinline__ void load_chunk_T(const float* __restrict__ src,
                                             float* __restrict__ XsT, int tid)
{
#pragma unroll
    for (int it = 0; it < (CHUNK * DDIM) / TBLK; it++) {
        int idx = tid + it * TBLK;
        int r = idx >> 6, d = idx & 63;
        XsT[d * XPAD + r] = src[r * DDIM + d];
    }
}

// ---------------------------------------------------------------------------
// Kernel A: k-side. smem = P(64K) + XsT(17K) + E(64K) + V(16K) = 164864 B
// ---------------------------------------------------------------------------
__global__ __launch_bounds__(TBLK, 1)
void favor_k_kernel(const float* __restrict__ K, const float* __restrict__ V,
                    const float* __restrict__ P)
{
    extern __shared__ float sm[];
    float* Ps  = sm;                    // [64][256]
    float* XsT = Ps + DDIM * FDIM;      // [64][XPAD]
    float* Es  = XsT + DDIM * XPAD;     // [64][256]
    float* Vs  = Es + CHUNK * FDIM;     // [64][64]

    const int tid = threadIdx.x;
    const int split = blockIdx.x, bh = blockIdx.y;
    const float* kb = K + (size_t)bh * NSEQ * DDIM;
    const float* vb = V + (size_t)bh * NSEQ * DDIM;

    {
        const float4* src = (const float4*)P;
        float4* dst = (float4*)Ps;
#pragma unroll
        for (int it = 0; it < (DDIM * FDIM / 4) / TBLK; it++)
            dst[tid + it * TBLK] = src[tid + it * TBLK];
    }

    const int rg = tid >> 5, cg = tid & 31;   // GEMM1 mapping
    const int fg = tid >> 3, dg = tid & 7;    // GEMM2 mapping

    // GEMM2 packed accumulators: kvp[hf][i2][hd][j] lanes = f pair
    // (hf*128+fg*4+2*i2, +1); cols d = hd*32+dg*4+j. ksp lanes likewise.
    u64 kvp[2][2][2][4];
    u64 ksp[2][2];
#pragma unroll
    for (int hf = 0; hf < 2; hf++)
#pragma unroll
        for (int i2 = 0; i2 < 2; i2++) {
            ksp[hf][i2] = 0ull;
#pragma unroll
            for (int hd = 0; hd < 2; hd++)
#pragma unroll
                for (int j = 0; j < 4; j++) kvp[hf][i2][hd][j] = 0ull;
        }

    for (int c = 0; c < NCHUNK; c++) {
        const int n0 = split * RPB + c * CHUNK;
        __syncthreads();
        load_chunk_T(kb + (size_t)n0 * DDIM, XsT, tid);
        {   // V chunk: contiguous copy
            const float4* src = (const float4*)(vb + (size_t)n0 * DDIM);
            float4* dst = (float4*)Vs;
#pragma unroll
            for (int it = 0; it < (CHUNK * DDIM / 4) / TBLK; it++)
                dst[tid + it * TBLK] = src[tid + it * TBLK];
        }
        __syncthreads();

        u64 accp[2][2][2][4];
        proj_gemm_pk(XsT, Ps, rg, cg, accp);
        float acc[2][2][4][4];
        unpack_acc(accp, acc);
        maxexp_rows(acc);
        store_E(Es, rg, cg, acc);
        __syncthreads();

        // GEMM2 (packed): kv[f][d] += sum_r E[r][f]*V[r][d]; ksum[f] += E[r][f]
        // a-pairs free from contiguous Es float4; V scalars lane-duplicated.
#pragma unroll 4
        for (int r = 0; r < CHUNK; r++) {
            ulonglong2 A0 = *(const ulonglong2*)(Es + r * FDIM + fg * 4);
            ulonglong2 A1 = *(const ulonglong2*)(Es + r * FDIM + 128 + fg * 4);
            u64 ap[2][2] = {{A0.x, A0.y}, {A1.x, A1.y}};
            float4 V0 = *(const float4*)(Vs + r * DDIM + dg * 4);
            float4 V1 = *(const float4*)(Vs + r * DDIM + 32 + dg * 4);
            u64 bd[2][4] = {{dup2(V0.x), dup2(V0.y), dup2(V0.z), dup2(V0.w)},
                            {dup2(V1.x), dup2(V1.y), dup2(V1.z), dup2(V1.w)}};
#pragma unroll
            for (int hf = 0; hf < 2; hf++)
#pragma unroll
                for (int i2 = 0; i2 < 2; i2++) {
                    fadd2(ksp[hf][i2], ap[hf][i2]);
#pragma unroll
                    for (int hd = 0; hd < 2; hd++)
#pragma unroll
                        for (int j = 0; j < 4; j++)
                            ffma2(kvp[hf][i2][hd][j], ap[hf][i2], bd[hd][j]);
                }
        }
    }

    // Write per-split partials (no atomics -> deterministic)
    float* pkv = g_part_kv + ((size_t)(bh * NSPLIT + split)) * FDIM * DDIM;
    float* pks = g_part_ks + (size_t)(bh * NSPLIT + split) * FDIM;
#pragma unroll
    for (int hf = 0; hf < 2; hf++)
#pragma unroll
        for (int i2 = 0; i2 < 2; i2++) {
            float rowlo[2][4], rowhi[2][4];
#pragma unroll
            for (int hd = 0; hd < 2; hd++)
#pragma unroll
                for (int j = 0; j < 4; j++)
                    upk2(rowlo[hd][j], rowhi[hd][j], kvp[hf][i2][hd][j]);
            float kslo, kshi;
            upk2(kslo, kshi, ksp[hf][i2]);

            int flo = hf * 128 + fg * 4 + 2 * i2;
#pragma unroll
            for (int hd = 0; hd < 2; hd++) {
                int d = hd * 32 + dg * 4;
                *(float4*)(pkv + flo * DDIM + d) =
                    make_float4(rowlo[hd][0], rowlo[hd][1], rowlo[hd][2], rowlo[hd][3]);
                *(float4*)(pkv + (flo + 1) * DDIM + d) =
                    make_float4(rowhi[hd][0], rowhi[hd][1], rowhi[hd][2], rowhi[hd][3]);
            }
            if (dg == 0) { pks[flo] = kslo; pks[flo + 1] = kshi; }
        }
}

// ---------------------------------------------------------------------------
// Reduce: sum NSPLIT partials deterministically; add 1e-6 to ksum here.
// ---------------------------------------------------------------------------
__global__ void favor_reduce_kernel()
{
    int idx = blockIdx.x * blockDim.x + threadIdx.x;
    if (idx < BHN * FDIM * DDIM) {
        int bh = idx / (FDIM * DDIM), r = idx % (FDIM * DDIM);
        float s = 0.f;
#pragma unroll 8
        for (int sp = 0; sp < NSPLIT; sp++)
            s += g_part_kv[((size_t)bh * NSPLIT + sp) * FDIM * DDIM + r];
        g_kv[idx] = s;
    }
    if (idx < BHN * FDIM) {
        int bh = idx / FDIM, f = idx % FDIM;
        float s = 0.f;
#pragma unroll 8
        for (int sp = 0; sp < NSPLIT; sp++)
            s += g_part_ks[(bh * NSPLIT + sp) * FDIM + f];
        g_ks[idx] = s + 1e-6f;
    }
}

// ---------------------------------------------------------------------------
// Kernel B: q-side + output.
// smem = P(64K) + kv(64K) + XsT(17K) + E(64K) + kse(1K) + dnm = 215296 B
// ---------------------------------------------------------------------------
__global__ __launch_bounds__(TBLK, 1)
void favor_q_kernel(const float* __restrict__ Q, const float* __restrict__ P,
                    float* __restrict__ Out)
{
    extern __shared__ float sm[];
    float* Ps  = sm;                    // [64][256]
    float* KVs = Ps + DDIM * FDIM;      // [256][64]
    float* XsT = KVs + FDIM * DDIM;     // [64][XPAD]
    float* Es  = XsT + DDIM * XPAD;     // [64][256]
    float* KSe = Es + CHUNK * FDIM;     // [256]
    float* Dnm = KSe + FDIM;            // [64]

    const int tid = threadIdx.x;
    const int split = blockIdx.x, bh = blockIdx.y;
    const float* qb = Q + (size_t)bh * NSEQ * DDIM;
    float* ob = Out + (size_t)bh * NSEQ * DDIM;

    {
        const float4* src = (const float4*)P;
        float4* dst = (float4*)Ps;
#pragma unroll
        for (int it = 0; it < (DDIM * FDIM / 4) / TBLK; it++)
            dst[tid + it * TBLK] = src[tid + it * TBLK];
        const float4* ksrc = (const float4*)(g_kv + (size_t)bh * FDIM * DDIM);
        float4* kdst = (float4*)KVs;
#pragma unroll
        for (int it = 0; it < (FDIM * DDIM / 4) / TBLK; it++)
            kdst[tid + it * TBLK] = ksrc[tid + it * TBLK];
        KSe[tid] = g_ks[bh * FDIM + tid];   // includes +1e-6
    }

    const int rg = tid >> 5, cg = tid & 31;
    const int w = tid >> 5, lane = tid & 31;

    for (int c = 0; c < NCHUNK; c++) {
        const int n0 = split * RPB + c * CHUNK;
        __syncthreads();
        load_chunk_T(qb + (size_t)n0 * DDIM, XsT, tid);
        __syncthreads();

        u64 accp[2][2][2][4];
        proj_gemm_pk(XsT, Ps, rg, cg, accp);
        float acc[2][2][4][4];
        unpack_acc(accp, acc);
        maxexp_rows(acc);

        // denom[r] = sum_f E[r][f] * kse[f]  (folded into GEMM1 epilogue)
        {
            float4 K0 = *(const float4*)(KSe + cg * 4);
            float4 K1 = *(const float4*)(KSe + 128 + cg * 4);
            float kv0[4] = {K0.x, K0.y, K0.z, K0.w};
            float kv1[4] = {K1.x, K1.y, K1.z, K1.w};
#pragma unroll
            for (int hr = 0; hr < 2; hr++)
#pragma unroll
                for (int i = 0; i < 4; i++) {
                    float dn = 0.f;
#pragma unroll
                    for (int j = 0; j < 4; j++)
                        dn += acc[hr][0][i][j] * kv0[j] + acc[hr][1][i][j] * kv1[j];
#pragma unroll
                    for (int off = 16; off > 0; off >>= 1)
                        dn += __shfl_xor_sync(0xffffffffu, dn, off);
                    if (cg == 0) Dnm[hr * 32 + rg * 4 + i] = dn;
                }
        }
        store_E(Es, rg, cg, acc);
        __syncthreads();

        // GEMM3 (packed over the f reduction): out[r][d] = sum_f E[r][f]*kv[f][d].
        // Warp w owns rows w*8..w*8+7; lanes keep f-even/f-odd partial sums,
        // combined once at the end. a-pairs free from Es float4 loads.
        u64 oap[8][2];
#pragma unroll
        for (int i = 0; i < 8; i++) { oap[i][0] = 0ull; oap[i][1] = 0ull; }
#pragma unroll 2
        for (int f0 = 0; f0 < FDIM; f0 += 4) {
            u64 ap[8][2];
#pragma unroll
            for (int i = 0; i < 8; i++) {
                ulonglong2 A = *(const ulonglong2*)(Es + (w * 8 + i) * FDIM + f0); // bcast
                ap[i][0] = A.x; ap[i][1] = A.y;
            }
            float b0[4], b1[4];
#pragma unroll
            for (int u = 0; u < 4; u++) {
                b0[u] = KVs[(f0 + u) * DDIM + lane];          // conflict-free
                b1[u] = KVs[(f0 + u) * DDIM + 32 + lane];
            }
            u64 bp0[2] = {pk2(b0[0], b0[1]), pk2(b0[2], b0[3])};
            u64 bp1[2] = {pk2(b1[0], b1[1]), pk2(b1[2], b1[3])};
#pragma unroll
            for (int i = 0; i < 8; i++)
#pragma unroll
                for (int u2 = 0; u2 < 2; u2++) {
                    ffma2(oap[i][0], ap[i][u2], bp0[u2]);
                    ffma2(oap[i][1], ap[i][u2], bp1[u2]);
                }
        }
#pragma unroll
        for (int i = 0; i < 8; i++) {
            float lo0, hi0, lo1, hi1;
            upk2(lo0, hi0, oap[i][0]);
            upk2(lo1, hi1, oap[i][1]);
            float rz = 1.0f / Dnm[w * 8 + i];
            size_t r = (size_t)(n0 + w * 8 + i) * DDIM;
            ob[r + lane]      = (lo0 + hi0) * rz;
            ob[r + 32 + lane] = (lo1 + hi1) * rz;
        }
    }
}

// ---------------------------------------------------------------------------
extern "C" void kernel_launch(void* const* d_in, const int* in_sizes, int n_in,
                              void* d_out, int out_size)
{
    const float* q = (const float*)d_in[0];
    const float* k = (const float*)d_in[1];
    const float* v = (const float*)d_in[2];
    const float* P = (const float*)d_in[3];
    float* out = (float*)d_out;

    const int A_SMEM = (DDIM * FDIM + DDIM * XPAD + CHUNK * FDIM + CHUNK * DDIM) * 4;
    const int B_SMEM = (DDIM * FDIM + FDIM * DDIM + DDIM * XPAD + CHUNK * FDIM + FDIM + 64) * 4;

    cudaFuncSetAttribute(favor_k_kernel, cudaFuncAttributeMaxDynamicSharedMemorySize, A_SMEM);
    cudaFuncSetAttribute(favor_q_kernel, cudaFuncAttributeMaxDynamicSharedMemorySize, B_SMEM);

    dim3 grid(NSPLIT, BHN);
    favor_k_kernel<<<grid, TBLK, A_SMEM>>>(k, v, P);
    favor_reduce_kernel<<<(BHN * FDIM * DDIM + 255) / 256, 256>>>();
    favor_q_kernel<<<grid, TBLK, B_SMEM>>>(q, P, out);
}